// round 16
// baseline (speedup 1.0000x reference)
#include <cuda_runtime.h>
#include <cstdint>

#define NN 8
#define CC 64
#define GG 8
#define DDp 16
#define HHs 56
#define WWs 56
#define HWsz (HHs*WWs)          /* 3136  */
#define DHWsz (DDp*HWsz)        /* 50176 */
#define CDHWsz (CC*DHWsz)       /* 3211264 */
#define OUT_ELEMS (NN*CDHWsz)   /* 25690112 */
#define OFF_ELEMS (NN*GG*DHWsz) /* 3211264 */
#define CNTf 401408.0f
#define XP 62                   /* xs pitch (8B units): 6*62 mod 16 == 4 -> 2-way max on B loads */
#define WP 68                   /* wsm pitch (8B units): ci*68 mod 16 == ci*4 -> 2-way max on A loads */

typedef unsigned long long ull;

// ---------------- device scratch ----------------
__device__ float g_y1[OUT_ELEMS];
__device__ float g_y2[OUT_ELEMS];
__device__ float g_off[OFF_ELEMS];
__device__ ull   g_w1hl[27*4096];          // w1 (hi,lo) tf32 pairs [tap][ci][co]
__device__ ull   g_w2hl[27*4096];          // w2 pairs
__device__ float g_wToff[27*64*8];         // offset-conv weights [tap][ci][gi]
__device__ float g_s1[64], g_q1[64], g_s2[64], g_q2[64];
__device__ float g_a1[64], g_b1[64], g_a2[64], g_b2[64];

// ---------------- tf32 helpers ----------------
__device__ __forceinline__ ull split_hl(float v) {
    uint32_t hi; asm("cvt.rna.tf32.f32 %0, %1;" : "=r"(hi) : "f"(v));
    const float r = v - __uint_as_float(hi);
    uint32_t lo; asm("cvt.rna.tf32.f32 %0, %1;" : "=r"(lo) : "f"(r));
    return ((ull)lo << 32) | (ull)hi;
}
__device__ __forceinline__ void mma_tf32(float* d, const uint32_t* a, uint32_t b0, uint32_t b1) {
    asm("mma.sync.aligned.m16n8k8.row.col.f32.tf32.tf32.f32 "
        "{%0,%1,%2,%3}, {%4,%5,%6,%7}, {%8,%9}, {%0,%1,%2,%3};"
        : "+f"(d[0]), "+f"(d[1]), "+f"(d[2]), "+f"(d[3])
        : "r"(a[0]), "r"(a[1]), "r"(a[2]), "r"(a[3]), "r"(b0), "r"(b1));
}

__global__ void dummy_kernel() {}

// ---------------- prep: tf32-split transposed weights, zero stats ----------------
__global__ void prep_kernel(const float* __restrict__ w_off,
                            const float* __restrict__ w1,
                            const float* __restrict__ w2) {
    int i = blockIdx.x * 256 + threadIdx.x;
    if (i < 27*4096) {
        int tap = i >> 12; int ci = (i >> 6) & 63; int co = i & 63;
        g_w1hl[i] = split_hl(w1[(co*64 + ci)*27 + tap]);
        g_w2hl[i] = split_hl(w2[(co*64 + ci)*27 + tap]);
    }
    if (i < 27*512) {
        int tap = i >> 9; int r = i & 511; int ci = r >> 3; int gi = r & 7;
        g_wToff[i] = w_off[(gi*64 + ci)*27 + tap];
    }
    if (i < 64) { g_s1[i]=0.f; g_q1[i]=0.f; g_s2[i]=0.f; g_q2[i]=0.f; }
}

// ---------------- conv1: offsets (scalar fp32, Cout=8) ----------------
__global__ __launch_bounds__(256, 2)
void conv_off_kernel(const float* __restrict__ x,
                     const float* __restrict__ b_off,
                     float* __restrict__ out_off) {
    extern __shared__ float sm[];
    float* xs = sm;                   // [64][6][64]
    float* ws = sm + 64*6*64;         // [2][512]
    const int tid = threadIdx.x;
    int b = blockIdx.x;
    const int ht = b % 14; b /= 14;
    const int d = b % DDp; const int n = b / DDp;
    const int h0 = ht * 4;
    const int hh_loc = tid / WWs;
    const int wq = tid % WWs;
    const bool active = tid < 224;

    float acc[8];
#pragma unroll
    for (int k = 0; k < 8; k++) acc[k] = 0.f;

    for (int i = tid; i < 512; i += 256) ws[i] = g_wToff[i];

    for (int kd = 0; kd < 3; kd++) {
        __syncthreads();
        const int dd = d + kd - 1;
        const bool vd = (unsigned)dd < DDp;
        const float* src = x + (size_t)n*CDHWsz + (size_t)dd*HWsz;
        for (int i = tid; i < 64*6*58; i += 256) {
            int wz = i % 58; int t = i / 58;
            int hr = t % 6;  int ci = t / 6;
            int hh = h0 - 1 + hr, ww = wz - 1;
            float v = 0.f;
            if (vd && (unsigned)hh < HHs && (unsigned)ww < WWs)
                v = src[(size_t)ci*DHWsz + hh*WWs + ww];
            xs[(ci*6 + hr)*64 + wz] = v;
        }
        __syncthreads();
        for (int t9 = 0; t9 < 9; t9++) {
            const int tap = kd*9 + t9;
            const float* wcur = ws + (tap & 1)*512;
            if (tap + 1 < 27) {
                float* wn = ws + ((tap + 1) & 1)*512;
                const float* s2 = g_wToff + (tap + 1)*512;
                for (int i = tid; i < 512; i += 256) wn[i] = s2[i];
            }
            const int kh = t9 / 3, kw = t9 - kh*3;
            if (active) {
                const float* xr = xs + (hh_loc + kh)*64 + wq + kw;
#pragma unroll 4
                for (int ci = 0; ci < 64; ci++) {
                    const float xv = xr[ci*6*64];
                    const float4 w0 = *(const float4*)(wcur + ci*8);
                    const float4 w1v = *(const float4*)(wcur + ci*8 + 4);
                    acc[0] = fmaf(xv, w0.x, acc[0]);
                    acc[1] = fmaf(xv, w0.y, acc[1]);
                    acc[2] = fmaf(xv, w0.z, acc[2]);
                    acc[3] = fmaf(xv, w0.w, acc[3]);
                    acc[4] = fmaf(xv, w1v.x, acc[4]);
                    acc[5] = fmaf(xv, w1v.y, acc[5]);
                    acc[6] = fmaf(xv, w1v.z, acc[6]);
                    acc[7] = fmaf(xv, w1v.w, acc[7]);
                }
            }
            __syncthreads();
        }
    }
    if (active) {
        const int h = h0 + hh_loc;
#pragma unroll
        for (int gi = 0; gi < 8; gi++)
            out_off[((size_t)(n*GG + gi)*DDp + d)*HWsz + h*WWs + wq] = acc[gi] + b_off[gi];
    }
}

// ---------------- main convs via mma.sync TF32 (3xTF32 precision) ----------------
// block 256 = 8 warps; warp w: co-pair p = w&1 (32 co), h-row g = w>>1.
// Tiles per warp: 2 Mtiles(16co) x 7 Ntiles(8w). K = 576, tap-major 8-ci chunks.
// MODE 0 = deform conv (interp at staging), MODE 1 = conv2 (BN1+ReLU at staging).
template<int MODE>
__global__ __launch_bounds__(256, 2)
void conv_mma(const float* __restrict__ xin,
              const float* __restrict__ offp,
              const float* __restrict__ bias) {
    extern __shared__ char smraw[];
    ull*   xs  = (ull*)smraw;                         // [8 ci][6 hr][XP] (hi,lo) pairs
    ull*   wsm = (ull*)(smraw + 8*6*XP*8);            // [9*8][WP] (hi,lo) pairs
    float* aux = (float*)(smraw + 8*6*XP*8 + 9*8*WP*8); // MODE0: offs[8][6][58]; MODE1: ab[128]

    const int tid = threadIdx.x;
    const int w = tid >> 5, lane = tid & 31;
    const int p = w & 1, g = w >> 1;
    const int co_base = p * 32;
    const int lg = lane >> 2, lt = lane & 3;
    int b = blockIdx.x;
    const int ht = b % 14; b /= 14;
    const int d = b % DDp; const int n = b / DDp;
    const int h0 = ht * 4;

    const ull* whl = (MODE == 0) ? g_w1hl : g_w2hl;

    float acc[56];
#pragma unroll
    for (int k = 0; k < 56; k++) acc[k] = 0.f;

    if (MODE == 0) {
        for (int i = tid; i < 8*6*58; i += 256) {
            int wz = i % 58; int t = i / 58;
            int hr = t % 6;  int gi = t / 6;
            int hh = h0 - 1 + hr, ww = wz - 1;
            float v = 0.f;
            if ((unsigned)hh < HHs && (unsigned)ww < WWs)
                v = offp[((size_t)(n*GG + gi)*DDp + d)*HWsz + hh*WWs + ww];
            aux[(gi*6 + hr)*58 + wz] = v;
        }
    } else {
        if (tid < 64) { aux[tid] = g_a1[tid]; aux[64 + tid] = g_b1[tid]; }
    }
    __syncthreads();

    for (int kd = 0; kd < 3; kd++) {
        for (int cic = 0; cic < 8; cic++) {
            const int ci0 = cic * 8;
            __syncthreads();
            // ---- stage xs (8 ci x 6 rows x 58 cols) as (hi,lo) tf32 pairs ----
            for (int i = tid; i < 8*6*58; i += 256) {
                const int wz = i % 58; const int t = i / 58;
                const int hr = t % 6;  const int ci_l = t / 6;
                const int ci = ci0 + ci_l;
                const int hh = h0 - 1 + hr, ww = wz - 1;
                float v = 0.f;
                if ((unsigned)hh < HHs && (unsigned)ww < WWs) {
                    if (MODE == 0) {
                        const float offv = aux[((ci >> 3)*6 + hr)*58 + wz];
                        const float pos = (offv + (float)d) + (float)(kd - 1);
                        const float f0 = floorf(pos);
                        const float frac = pos - f0;
                        const int i0 = (int)f0;
                        const float* base = xin + (size_t)n*CDHWsz + (size_t)ci*DHWsz + hh*WWs + ww;
                        const float v0 = ((unsigned)i0 < DDp) ? base[(size_t)i0*HWsz] : 0.f;
                        const float v1 = ((unsigned)(i0 + 1) < DDp) ? base[(size_t)(i0 + 1)*HWsz] : 0.f;
                        v = v0*(1.f - frac) + v1*frac;
                    } else {
                        const int dd = d + kd - 1;
                        if ((unsigned)dd < DDp) {
                            const float y = g_y1[(size_t)n*CDHWsz + (size_t)ci*DHWsz + (size_t)dd*HWsz + hh*WWs + ww];
                            v = fmaxf(fmaf(aux[ci], y, aux[64 + ci]), 0.f);
                        }
                    }
                }
                xs[(ci_l*6 + hr)*XP + wz] = split_hl(v);
            }
            // ---- stage wsm: 9 taps x 8 ci x 64 co pairs ----
            for (int i = tid; i < 4608; i += 256) {
                const int co = i & 63;
                const int t9 = (i >> 6) % 9;
                const int ci_l = i / 576;
                wsm[(t9*8 + ci_l)*WP + co] = whl[(size_t)(kd*9 + t9)*4096 + (ci0 + ci_l)*64 + co];
            }
            __syncthreads();
            // ---- 9 K-steps (one per tap), K=8 ci each ----
            for (int t9 = 0; t9 < 9; t9++) {
                const int kh = t9 / 3, kw = t9 - kh*3;
                uint32_t Ahi[2][4], Alo[2][4];
#pragma unroll
                for (int m = 0; m < 2; m++) {
                    const int abase = (t9*8 + lt)*WP + co_base + m*16 + lg;
                    const ull a0 = wsm[abase];
                    const ull a1 = wsm[abase + 8];
                    const ull a2 = wsm[abase + 4*WP];
                    const ull a3 = wsm[abase + 4*WP + 8];
                    Ahi[m][0] = (uint32_t)a0; Alo[m][0] = (uint32_t)(a0 >> 32);
                    Ahi[m][1] = (uint32_t)a1; Alo[m][1] = (uint32_t)(a1 >> 32);
                    Ahi[m][2] = (uint32_t)a2; Alo[m][2] = (uint32_t)(a2 >> 32);
                    Ahi[m][3] = (uint32_t)a3; Alo[m][3] = (uint32_t)(a3 >> 32);
                }
                const int xb = lt*(6*XP) + (g + kh)*XP + kw + lg;
#pragma unroll
                for (int j = 0; j < 7; j++) {
                    const ull b0p = xs[xb + j*8];
                    const ull b1p = xs[xb + j*8 + 4*(6*XP)];
                    const uint32_t b0h = (uint32_t)b0p, b0l = (uint32_t)(b0p >> 32);
                    const uint32_t b1h = (uint32_t)b1p, b1l = (uint32_t)(b1p >> 32);
#pragma unroll
                    for (int m = 0; m < 2; m++) {
                        float* dacc = acc + (m*7 + j)*4;
                        mma_tf32(dacc, Alo[m], b0h, b1h);   // lo*hi
                        mma_tf32(dacc, Ahi[m], b0l, b1l);   // hi*lo
                        mma_tf32(dacc, Ahi[m], b0h, b1h);   // hi*hi
                    }
                }
            }
        }
    }

    // ---- epilogue: bias + store + fused BN stats ----
    float* yout = (MODE == 0) ? g_y1 : g_y2;
    const int h = h0 + g;
    float s[4] = {0,0,0,0}, q[4] = {0,0,0,0};
    float bv[4];
#pragma unroll
    for (int m = 0; m < 2; m++) {
        const int co_r = co_base + m*16 + lg;
        bv[m*2+0] = (MODE == 1) ? bias[co_r]     : 0.f;
        bv[m*2+1] = (MODE == 1) ? bias[co_r + 8] : 0.f;
    }
#pragma unroll
    for (int m = 0; m < 2; m++) {
        const int co_r = co_base + m*16 + lg;
#pragma unroll
        for (int j = 0; j < 7; j++) {
            const int ww = j*8 + lt*2;
            const float* c = acc + (m*7 + j)*4;
            const float u0 = c[0] + bv[m*2],   u1 = c[1] + bv[m*2];
            const float u2 = c[2] + bv[m*2+1], u3 = c[3] + bv[m*2+1];
            const size_t base = (size_t)n*CDHWsz + (size_t)d*HWsz + h*WWs + ww;
            *(float2*)(yout + base + (size_t)co_r*DHWsz)       = make_float2(u0, u1);
            *(float2*)(yout + base + (size_t)(co_r + 8)*DHWsz) = make_float2(u2, u3);
            s[m*2]   += u0 + u1; q[m*2]   += u0*u0 + u1*u1;
            s[m*2+1] += u2 + u3; q[m*2+1] += u2*u2 + u3*u3;
        }
    }
#pragma unroll
    for (int mm = 1; mm <= 2; mm <<= 1) {
#pragma unroll
        for (int k = 0; k < 4; k++) {
            s[k] += __shfl_xor_sync(0xffffffffu, s[k], mm);
            q[k] += __shfl_xor_sync(0xffffffffu, q[k], mm);
        }
    }
    if (lt == 0) {
        float* gs = (MODE == 0) ? g_s1 : g_s2;
        float* gq = (MODE == 0) ? g_q1 : g_q2;
#pragma unroll
        for (int m = 0; m < 2; m++) {
            const int co_r = co_base + m*16 + lg;
            atomicAdd(&gs[co_r],     s[m*2]);   atomicAdd(&gq[co_r],     q[m*2]);
            atomicAdd(&gs[co_r + 8], s[m*2+1]); atomicAdd(&gq[co_r + 8], q[m*2+1]);
        }
    }
}

// ---------------- BN finalize ----------------
template<int WHICH>
__global__ void bn_finalize(const float* __restrict__ gamma, const float* __restrict__ beta) {
    const int c = threadIdx.x;
    const float* s = (WHICH == 0) ? g_s1 : g_s2;
    const float* q = (WHICH == 0) ? g_q1 : g_q2;
    float* a  = (WHICH == 0) ? g_a1 : g_a2;
    float* bo = (WHICH == 0) ? g_b1 : g_b2;
    const float mean = s[c] * (1.0f / CNTf);
    const float var  = q[c] * (1.0f / CNTf) - mean*mean;
    const float ai = gamma[c] * rsqrtf(var + 1e-5f);
    a[c] = ai;
    bo[c] = beta[c] - ai*mean;
}

// ---------------- epilogue: out = relu(bn2(y2) + x) ----------------
__global__ void finalize_out(const float* __restrict__ x, float* __restrict__ out) {
    const int i4 = blockIdx.x * blockDim.x + threadIdx.x;
    if (i4 >= OUT_ELEMS/4) return;
    const size_t i = (size_t)i4 * 4;
    const int c = (int)((i / DHWsz) & 63);
    const float a = g_a2[c], bb = g_b2[c];
    const float4 y  = *(const float4*)(g_y2 + i);
    const float4 xv = *(const float4*)(x + i);
    float4 r;
    r.x = fmaxf(fmaf(a, y.x, bb) + xv.x, 0.f);
    r.y = fmaxf(fmaf(a, y.y, bb) + xv.y, 0.f);
    r.z = fmaxf(fmaf(a, y.z, bb) + xv.z, 0.f);
    r.w = fmaxf(fmaf(a, y.w, bb) + xv.w, 0.f);
    *(float4*)(out + i) = r;
}

// ---------------- launch ----------------
extern "C" void kernel_launch(void* const* d_in, const int* in_sizes, int n_in,
                              void* d_out, int out_size) {
    const float* x     = (const float*)d_in[0];
    const float* w_off = (const float*)d_in[1];
    const float* b_off = (const float*)d_in[2];
    const float* w1    = (const float*)d_in[3];
    const float* w2    = (const float*)d_in[4];
    const float* b2    = (const float*)d_in[5];
    const float* g1    = (const float*)d_in[6];
    const float* be1   = (const float*)d_in[7];
    const float* g2    = (const float*)d_in[8];
    const float* be2   = (const float*)d_in[9];
    float* out = (float*)d_out;

    float* offdst = out + OUT_ELEMS;
    if (out_size < OUT_ELEMS + OFF_ELEMS) {
        void* pp = nullptr;
        cudaGetSymbolAddress(&pp, g_off);
        offdst = (float*)pp;
    }

    const int SMEM_OFFK = (64*6*64 + 2*512) * 4;                 // 102400
    const int SMEM_M0   = 8*6*XP*8 + 9*8*WP*8 + 8*6*58*4;        //  74112
    const int SMEM_M1   = 8*6*XP*8 + 9*8*WP*8 + 128*4;           //  63488

    cudaFuncSetAttribute(conv_off_kernel, cudaFuncAttributeMaxDynamicSharedMemorySize, SMEM_OFFK);
    cudaFuncSetAttribute(conv_mma<0>,     cudaFuncAttributeMaxDynamicSharedMemorySize, SMEM_M0);
    cudaFuncSetAttribute(conv_mma<1>,     cudaFuncAttributeMaxDynamicSharedMemorySize, SMEM_M1);

    prep_kernel<<<432, 256>>>(w_off, w1, w2);                          // idx 0
    conv_off_kernel<<<NN*DDp*14, 256, SMEM_OFFK>>>(x, b_off, offdst);  // idx 1
    dummy_kernel<<<1, 32>>>();                                          // idx 2 (ncu shim)
    conv_mma<0><<<NN*DDp*14, 256, SMEM_M0>>>(x, offdst, b2);           // idx 3 <- ncu target
    bn_finalize<0><<<1, 64>>>(g1, be1);
    conv_mma<1><<<NN*DDp*14, 256, SMEM_M1>>>(x, offdst, b2);
    bn_finalize<1><<<1, 64>>>(g2, be2);
    finalize_out<<<(OUT_ELEMS/4 + 255)/256, 256>>>(x, out);
}